// round 2
// baseline (speedup 1.0000x reference)
#include <cuda_runtime.h>
#include <math.h>
#include <stdint.h>

// ---------------- problem constants ----------------
#define B   64
#define T   256
#define D   2048
#define H   1024
#define G3  3072          // 3*H
#define NC  1000
#define BT  (B*T)         // 16384

// ---------------- device scratch (no allocs allowed) ----------------
__device__ float g_M2 [3*2048];     // [g][i1][i2][o1][o2][r2]
__device__ float g_M34[3*16384];    // [g][r2][i3][i4][o3][o4]
__device__ float g_W  [D*G3];       // collapsed TT weight [d][j], j=g*1024+o
__device__ float g_UT [G3*H];       // U transposed: [j][k]
__device__ float g_gi [BT*G3];      // precomputed input gates (+bi)
__device__ float g_h  [2][B*H];     // ping-pong hidden state
__device__ unsigned g_barc;         // grid barrier count (returns to 0)
__device__ unsigned g_barg;         // grid barrier generation (monotone)

// ---------------- init: zero h[0] ----------------
__global__ void init_h_kernel() {
    int idx = blockIdx.x * blockDim.x + threadIdx.x;
    for (int i = idx; i < B*H; i += gridDim.x * blockDim.x)
        g_h[0][i] = 0.f;
}

// ---------------- build M2, M34 from TT cores ----------------
// core0 [3,1,4,4,4]  core1 [3,4,8,4,4]  core2 [3,4,8,8,4]  core3 [3,4,8,8,1]
__global__ void build_M_kernel(const float* __restrict__ c0,
                               const float* __restrict__ c1,
                               const float* __restrict__ c2,
                               const float* __restrict__ c3) {
    // M2[g][i1][i2][o1][o2][r2] = sum_r1 c0[g,0,i1,o1,r1]*c1[g,r1,i2,o2,r2]
    for (int idx = threadIdx.x; idx < 3*2048; idx += blockDim.x) {
        int r2 = idx & 3, o2 = (idx>>2)&3, o1 = (idx>>4)&3;
        int i2 = (idx>>6)&7, i1 = (idx>>9)&3, g = idx>>11;
        float s = 0.f;
        #pragma unroll
        for (int r1 = 0; r1 < 4; ++r1)
            s += c0[g*64 + i1*16 + o1*4 + r1] *
                 c1[g*512 + r1*128 + i2*16 + o2*4 + r2];
        g_M2[idx] = s;
    }
    // M34[g][r2][i3][i4][o3][o4] = sum_r3 c2[g,r2,i3,o3,r3]*c3[g,r3,i4,o4]
    for (int idx = threadIdx.x; idx < 3*16384; idx += blockDim.x) {
        int o4 = idx & 7, o3 = (idx>>3)&7, i4 = (idx>>6)&7;
        int i3 = (idx>>9)&7, r2 = (idx>>12)&3, g = idx>>14;
        float s = 0.f;
        #pragma unroll
        for (int r3 = 0; r3 < 4; ++r3)
            s += c2[g*1024 + r2*256 + i3*32 + o3*4 + r3] *
                 c3[g*256  + r3*64  + i4*8  + o4];
        g_M34[idx] = s;
    }
}

// ---------------- build W: grid = 256 blocks, one per (i1,i2,i3) ----------------
__global__ void build_W_kernel() {
    __shared__ float sM2[192];    // [g][o1][o2][r2] for fixed (i1,i2)
    __shared__ float sM34[6144];  // [g][r2][i4][o3o4] for fixed i3
    int bx = blockIdx.x;
    int i1 = bx >> 6, i2 = (bx >> 3) & 7, i3 = bx & 7;
    int tid = threadIdx.x;

    for (int l = tid; l < 192; l += blockDim.x) {
        int low = l & 63, g = l >> 6;
        sM2[l] = g_M2[g*2048 + i1*512 + i2*64 + low];
    }
    for (int l = tid; l < 6144; l += blockDim.x) {
        int low6 = l & 63, i4 = (l>>6)&7, r2 = (l>>9)&3, g = l>>11;
        sM34[l] = g_M34[g*16384 + r2*4096 + i3*512 + i4*64 + low6];
    }
    __syncthreads();

    for (int e = tid; e < 8*G3; e += blockDim.x) {
        int i4 = e / G3;
        int j  = e - i4*G3;
        int g  = j >> 10, o = j & 1023;
        int o1 = o >> 8, o2 = (o >> 6) & 3, o34 = o & 63;
        float v = 0.f;
        #pragma unroll
        for (int r2 = 0; r2 < 4; ++r2)
            v += sM2[g*64 + o1*16 + o2*4 + r2] *
                 sM34[g*2048 + r2*512 + i4*64 + o34];
        int d = i1*512 + i2*64 + i3*8 + i4;
        g_W[d*G3 + j] = v;
    }
}

// ---------------- transpose U [H,G3] -> UT [G3,H] ----------------
__global__ void build_UT_kernel(const float* __restrict__ U) {
    __shared__ float s[32][33];
    int j0 = blockIdx.x * 32;          // 96 tiles over G3
    int k0 = blockIdx.y * 32;          // 32 tiles over H
    int tx = threadIdx.x, ty = threadIdx.y;
    #pragma unroll
    for (int r = ty; r < 32; r += 8)
        s[r][tx] = U[(size_t)(k0 + r) * G3 + j0 + tx];
    __syncthreads();
    #pragma unroll
    for (int r = ty; r < 32; r += 8)
        g_UT[(size_t)(j0 + r) * H + k0 + tx] = s[tx][r];
}

// ---------------- gi GEMM: [16384,2048] @ [2048,3072] + bi ----------------
// 128x128 block tile, 256 threads, 8x8 register tile, BK=16
__global__ void __launch_bounds__(256, 2)
gemm_gi_kernel(const float* __restrict__ X, const float* __restrict__ bi) {
    __shared__ float As[16][132];
    __shared__ float Bs[16][128];

    const int tid = threadIdx.x;
    const int bx  = blockIdx.x;   // 0..23  (N tiles)
    const int by  = blockIdx.y;   // 0..127 (M tiles)
    const int tx  = tid & 15;
    const int ty  = tid >> 4;

    const int ar = tid >> 2;            // 0..63
    const int ak = (tid & 3) * 4;       // 0,4,8,12
    const int br = tid >> 5;            // 0..7
    const int bc = (tid & 31) * 4;      // 0..124

    const float* Xb = X + (size_t)by * 128 * D;
    const float* Wb = g_W + bx * 128;

    float acc[8][8];
    #pragma unroll
    for (int i = 0; i < 8; ++i)
        #pragma unroll
        for (int j = 0; j < 8; ++j) acc[i][j] = 0.f;

    for (int k0 = 0; k0 < D; k0 += 16) {
        float4 a0 = *(const float4*)(Xb + (size_t)ar        * D + k0 + ak);
        float4 a1 = *(const float4*)(Xb + (size_t)(ar + 64) * D + k0 + ak);
        float4 b0 = *(const float4*)(Wb + (size_t)(k0 + br)     * G3 + bc);
        float4 b1 = *(const float4*)(Wb + (size_t)(k0 + br + 8) * G3 + bc);

        As[ak+0][ar] = a0.x; As[ak+1][ar] = a0.y; As[ak+2][ar] = a0.z; As[ak+3][ar] = a0.w;
        As[ak+0][ar+64] = a1.x; As[ak+1][ar+64] = a1.y; As[ak+2][ar+64] = a1.z; As[ak+3][ar+64] = a1.w;
        *(float4*)&Bs[br][bc]     = b0;
        *(float4*)&Bs[br + 8][bc] = b1;
        __syncthreads();

        #pragma unroll
        for (int k = 0; k < 16; ++k) {
            float4 a01 = *(const float4*)&As[k][ty*8];
            float4 a23 = *(const float4*)&As[k][ty*8 + 4];
            float4 b01 = *(const float4*)&Bs[k][tx*8];
            float4 b23 = *(const float4*)&Bs[k][tx*8 + 4];
            float av[8] = {a01.x,a01.y,a01.z,a01.w,a23.x,a23.y,a23.z,a23.w};
            float bv[8] = {b01.x,b01.y,b01.z,b01.w,b23.x,b23.y,b23.z,b23.w};
            #pragma unroll
            for (int i = 0; i < 8; ++i)
                #pragma unroll
                for (int j = 0; j < 8; ++j)
                    acc[i][j] += av[i] * bv[j];
        }
        __syncthreads();
    }

    const int col0 = bx * 128 + tx * 8;
    float bv[8];
    #pragma unroll
    for (int j = 0; j < 8; ++j) bv[j] = bi[col0 + j];
    #pragma unroll
    for (int i = 0; i < 8; ++i) {
        size_t row = (size_t)by * 128 + ty * 8 + i;
        float4 v0 = make_float4(acc[i][0]+bv[0], acc[i][1]+bv[1], acc[i][2]+bv[2], acc[i][3]+bv[3]);
        float4 v1 = make_float4(acc[i][4]+bv[4], acc[i][5]+bv[5], acc[i][6]+bv[6], acc[i][7]+bv[7]);
        *(float4*)&g_gi[row * G3 + col0]     = v0;
        *(float4*)&g_gi[row * G3 + col0 + 4] = v1;
    }
}

// ---------------- persistent scan ----------------
#define SCAN_BLOCKS 128
#define KC 256
#define HS_STRIDE 65
#define SCAN_SMEM (KC * HS_STRIDE * 4)

__device__ __forceinline__ void grid_barrier() {
    __syncthreads();
    if (threadIdx.x == 0) {
        volatile unsigned* vg = &g_barg;
        unsigned my = *vg;
        __threadfence();
        if (atomicAdd(&g_barc, 1u) == SCAN_BLOCKS - 1u) {
            atomicExch(&g_barc, 0u);
            __threadfence();
            *vg = my + 1u;
        } else {
            while (*vg == my) {}
            __threadfence();
        }
    }
    __syncthreads();
}

__global__ void __launch_bounds__(256, 1)
scan_kernel(const float* __restrict__ bh) {
    extern __shared__ float h_s[];     // [KC][HS_STRIDE], transposed: h_s[k][b]
    const int tid  = threadIdx.x;
    const int oloc = tid & 7;
    const int bg   = tid >> 3;         // 0..31
    const int o    = blockIdx.x * 8 + oloc;
    const int b0   = bg * 2;

    const float bh0 = bh[o];
    const float bh1 = bh[H + o];
    const float bh2 = bh[2*H + o];

    const float* u0 = g_UT + (size_t)(o)        * H;
    const float* u1 = g_UT + (size_t)(H + o)    * H;
    const float* u2 = g_UT + (size_t)(2*H + o)  * H;

    for (int t = 0; t < T; ++t) {
        const float* hc = g_h[t & 1];
        float*       hn = g_h[(t & 1) ^ 1];

        // prefetch input-gate values for this step (hidden by GEMM below)
        float gi0a = g_gi[((size_t)(b0     ) * T + t) * G3 +          o];
        float gi1a = g_gi[((size_t)(b0     ) * T + t) * G3 + H      + o];
        float gi2a = g_gi[((size_t)(b0     ) * T + t) * G3 + 2*H    + o];
        float gi0b = g_gi[((size_t)(b0 + 1 ) * T + t) * G3 +          o];
        float gi1b = g_gi[((size_t)(b0 + 1 ) * T + t) * G3 + H      + o];
        float gi2b = g_gi[((size_t)(b0 + 1 ) * T + t) * G3 + 2*H    + o];

        float a00=0.f,a01=0.f,a02=0.f,a10=0.f,a11=0.f,a12=0.f;

        for (int k0 = 0; k0 < H; k0 += KC) {
            __syncthreads();
            // stage h chunk transposed: h_s[k][b]
            for (int idx = tid; idx < KC * B; idx += 256) {
                int kk = idx & (KC - 1);
                int bb = idx >> 8;       // KC==256
                h_s[kk * HS_STRIDE + bb] = hc[bb * H + k0 + kk];
            }
            __syncthreads();

            const float4* up0 = (const float4*)(u0 + k0);
            const float4* up1 = (const float4*)(u1 + k0);
            const float4* up2 = (const float4*)(u2 + k0);

            #pragma unroll 4
            for (int kk = 0; kk < KC; kk += 4) {
                float4 w0 = up0[kk >> 2];
                float4 w1 = up1[kk >> 2];
                float4 w2 = up2[kk >> 2];
                float hv0[4], hv1[4];
                #pragma unroll
                for (int q = 0; q < 4; ++q) {
                    int a = (kk + q) * HS_STRIDE + b0;
                    hv0[q] = h_s[a];
                    hv1[q] = h_s[a + 1];
                }
                a00 += hv0[0]*w0.x + hv0[1]*w0.y + hv0[2]*w0.z + hv0[3]*w0.w;
                a01 += hv0[0]*w1.x + hv0[1]*w1.y + hv0[2]*w1.z + hv0[3]*w1.w;
                a02 += hv0[0]*w2.x + hv0[1]*w2.y + hv0[2]*w2.z + hv0[3]*w2.w;
                a10 += hv1[0]*w0.x + hv1[1]*w0.y + hv1[2]*w0.z + hv1[3]*w0.w;
                a11 += hv1[0]*w1.x + hv1[1]*w1.y + hv1[2]*w1.z + hv1[3]*w1.w;
                a12 += hv1[0]*w2.x + hv1[1]*w2.y + hv1[2]*w2.z + hv1[3]*w2.w;
            }
        }

        // GRU pointwise update (this thread owns all 3 gates of (b0,o),(b0+1,o))
        {
            float ghn = a02 + bh2;
            float r = 1.f / (1.f + expf(-(gi0a + a00 + bh0)));
            float z = 1.f / (1.f + expf(-(gi1a + a01 + bh1)));
            float n = tanhf(gi2a + r * ghn);
            float ho = hc[b0 * H + o];
            hn[b0 * H + o] = (1.f - z) * n + z * ho;
        }
        {
            float ghn = a12 + bh2;
            float r = 1.f / (1.f + expf(-(gi0b + a10 + bh0)));
            float z = 1.f / (1.f + expf(-(gi1b + a11 + bh1)));
            float n = tanhf(gi2b + r * ghn);
            float ho = hc[(b0 + 1) * H + o];
            hn[(b0 + 1) * H + o] = (1.f - z) * n + z * ho;
        }

        grid_barrier();
    }
}

// ---------------- final FC + ReLU ----------------
__global__ void fc_kernel(const float* __restrict__ Wfc,
                          const float* __restrict__ bfc,
                          float* __restrict__ out) {
    int idx = blockIdx.x * blockDim.x + threadIdx.x;
    if (idx >= B * NC) return;
    int b = idx / NC, c = idx - b * NC;
    const float* h = g_h[0] + (size_t)b * H;   // T even -> final state in buffer 0
    float s0 = bfc[c], s1 = 0.f, s2 = 0.f, s3 = 0.f;
    #pragma unroll 4
    for (int k = 0; k < H; k += 4) {
        float4 hv = *(const float4*)(h + k);
        s0 += hv.x * Wfc[(size_t)(k    ) * NC + c];
        s1 += hv.y * Wfc[(size_t)(k + 1) * NC + c];
        s2 += hv.z * Wfc[(size_t)(k + 2) * NC + c];
        s3 += hv.w * Wfc[(size_t)(k + 3) * NC + c];
    }
    float s = (s0 + s1) + (s2 + s3);
    out[idx] = fmaxf(s, 0.f);
}

// ---------------- launcher ----------------
extern "C" void kernel_launch(void* const* d_in, const int* in_sizes, int n_in,
                              void* d_out, int out_size) {
    (void)in_sizes; (void)n_in; (void)out_size;
    const float* x    = (const float*)d_in[0];
    const float* c0   = (const float*)d_in[1];
    const float* c1   = (const float*)d_in[2];
    const float* c2   = (const float*)d_in[3];
    const float* c3   = (const float*)d_in[4];
    const float* bi   = (const float*)d_in[5];
    const float* U    = (const float*)d_in[6];
    const float* bh   = (const float*)d_in[7];
    const float* Wfc  = (const float*)d_in[8];
    const float* bfc  = (const float*)d_in[9];
    // d_in[10] = length (fixed 256)

    cudaFuncSetAttribute(scan_kernel, cudaFuncAttributeMaxDynamicSharedMemorySize, SCAN_SMEM);

    init_h_kernel<<<64, 256>>>();
    build_M_kernel<<<1, 256>>>(c0, c1, c2, c3);
    build_W_kernel<<<256, 256>>>();
    build_UT_kernel<<<dim3(96, 32), dim3(32, 8)>>>(U);
    gemm_gi_kernel<<<dim3(24, 128), 256>>>(x, bi);
    scan_kernel<<<SCAN_BLOCKS, 256, SCAN_SMEM>>>(bh);
    fc_kernel<<<(B * NC + 255) / 256, 256>>>(Wfc, bfc, (float*)d_out);
}

// round 3
// speedup vs baseline: 2.6284x; 2.6284x over previous
#include <cuda_runtime.h>
#include <math.h>
#include <stdint.h>

typedef unsigned long long ull;

// ---------------- problem constants ----------------
#define B   64
#define T   256
#define D   2048
#define H   1024
#define G3  3072          // 3*H
#define NC  1000
#define BT  (B*T)         // 16384

// packed fp32x2 FMA (full-rate fp32 path on sm_100)
#define FMA_F32X2(acc, a, b) \
    asm("fma.rn.f32x2 %0, %1, %2, %0;" : "+l"(acc) : "l"(a), "l"(b))

// ---------------- device scratch (no allocs allowed) ----------------
__device__ float g_M2 [3*2048];     // [g][i1][i2][o1][o2][r2]
__device__ float g_M34[3*16384];    // [g][r2][i3][i4][o3][o4]
__device__ float g_W  [D*G3];       // collapsed TT weight [d][j], j=g*1024+o
__device__ float g_UT [G3*H];       // U transposed: [j][k]
__device__ float g_gi [BT*G3];      // input gates, layout [t][b][3H]
__device__ float g_h2 [2][(B/2)*H*2]; // ping-pong hidden, layout [b2][k][2]
__device__ unsigned g_barc;
__device__ unsigned g_barg;

// ---------------- init: zero h buffer 0 ----------------
__global__ void init_h_kernel() {
    int idx = blockIdx.x * blockDim.x + threadIdx.x;
    for (int i = idx; i < B*H; i += gridDim.x * blockDim.x)
        g_h2[0][i] = 0.f;
}

// ---------------- build M2, M34 from TT cores ----------------
__global__ void build_M_kernel(const float* __restrict__ c0,
                               const float* __restrict__ c1,
                               const float* __restrict__ c2,
                               const float* __restrict__ c3) {
    for (int idx = threadIdx.x; idx < 3*2048; idx += blockDim.x) {
        int r2 = idx & 3, o2 = (idx>>2)&3, o1 = (idx>>4)&3;
        int i2 = (idx>>6)&7, i1 = (idx>>9)&3, g = idx>>11;
        float s = 0.f;
        #pragma unroll
        for (int r1 = 0; r1 < 4; ++r1)
            s += c0[g*64 + i1*16 + o1*4 + r1] *
                 c1[g*512 + r1*128 + i2*16 + o2*4 + r2];
        g_M2[idx] = s;
    }
    for (int idx = threadIdx.x; idx < 3*16384; idx += blockDim.x) {
        int o4 = idx & 7, o3 = (idx>>3)&7, i4 = (idx>>6)&7;
        int i3 = (idx>>9)&7, r2 = (idx>>12)&3, g = idx>>14;
        float s = 0.f;
        #pragma unroll
        for (int r3 = 0; r3 < 4; ++r3)
            s += c2[g*1024 + r2*256 + i3*32 + o3*4 + r3] *
                 c3[g*256  + r3*64  + i4*8  + o4];
        g_M34[idx] = s;
    }
}

// ---------------- build W: 256 blocks, one per (i1,i2,i3) ----------------
__global__ void build_W_kernel() {
    __shared__ float sM2[192];
    __shared__ float sM34[6144];
    int bx = blockIdx.x;
    int i1 = bx >> 6, i2 = (bx >> 3) & 7, i3 = bx & 7;
    int tid = threadIdx.x;

    for (int l = tid; l < 192; l += blockDim.x) {
        int low = l & 63, g = l >> 6;
        sM2[l] = g_M2[g*2048 + i1*512 + i2*64 + low];
    }
    for (int l = tid; l < 6144; l += blockDim.x) {
        int low6 = l & 63, i4 = (l>>6)&7, r2 = (l>>9)&3, g = l>>11;
        sM34[l] = g_M34[g*16384 + r2*4096 + i3*512 + i4*64 + low6];
    }
    __syncthreads();

    for (int e = tid; e < 8*G3; e += blockDim.x) {
        int i4 = e / G3;
        int j  = e - i4*G3;
        int g  = j >> 10, o = j & 1023;
        int o1 = o >> 8, o2 = (o >> 6) & 3, o34 = o & 63;
        float v = 0.f;
        #pragma unroll
        for (int r2 = 0; r2 < 4; ++r2)
            v += sM2[g*64 + o1*16 + o2*4 + r2] *
                 sM34[g*2048 + r2*512 + i4*64 + o34];
        int d = i1*512 + i2*64 + i3*8 + i4;
        g_W[d*G3 + j] = v;
    }
}

// ---------------- transpose U [H,G3] -> UT [G3,H] ----------------
__global__ void build_UT_kernel(const float* __restrict__ U) {
    __shared__ float s[32][33];
    int j0 = blockIdx.x * 32;
    int k0 = blockIdx.y * 32;
    int tx = threadIdx.x, ty = threadIdx.y;
    #pragma unroll
    for (int r = ty; r < 32; r += 8)
        s[r][tx] = U[(size_t)(k0 + r) * G3 + j0 + tx];
    __syncthreads();
    #pragma unroll
    for (int r = ty; r < 32; r += 8)
        g_UT[(size_t)(j0 + r) * H + k0 + tx] = s[tx][r];
}

// ---------------- gi GEMM: [16384,2048]@[2048,3072] + bi, f32x2 path ------
// 128x128 tile, BK=8, 256 threads, 8x8 microtile as 8x(4 f32x2 pairs),
// A staged DUPLICATED in smem so both MMA operands load pre-packed.
#define NKT (D/8)            // 256 K-tiles
__global__ void __launch_bounds__(256)
gemm_gi_kernel(const float* __restrict__ X, const float* __restrict__ bi) {
    __shared__ __align__(16) float As2[2][8][260];  // dup'd: [k][2*row{,+1}]
    __shared__ __align__(16) float Bs [2][8][128];

    const int tid = threadIdx.x;
    const int bx  = blockIdx.x;     // 0..23
    const int by  = blockIdx.y;     // 0..127
    const int tx  = tid & 15;
    const int ty  = tid >> 4;

    const int arow = tid >> 1;          // 0..127
    const int ak   = (tid & 1) * 4;     // 0 or 4
    const int bk   = tid >> 5;          // 0..7
    const int bc   = (tid & 31) * 4;    // 0..124

    const float* Ag = X   + ((size_t)by * 128 + arow) * D + ak;
    const float* Bg = g_W + (size_t)bk * G3 + bx * 128 + bc;

    ull acc[8][4];
    #pragma unroll
    for (int i = 0; i < 8; ++i)
        #pragma unroll
        for (int j = 0; j < 4; ++j) acc[i][j] = 0ULL;

    float4 a4 = *(const float4*)Ag;
    float4 b4 = *(const float4*)Bg;

    // stage tile 0
    {
        *(float2*)&As2[0][ak+0][2*arow] = make_float2(a4.x, a4.x);
        *(float2*)&As2[0][ak+1][2*arow] = make_float2(a4.y, a4.y);
        *(float2*)&As2[0][ak+2][2*arow] = make_float2(a4.z, a4.z);
        *(float2*)&As2[0][ak+3][2*arow] = make_float2(a4.w, a4.w);
        *(float4*)&Bs[0][bk][bc] = b4;
    }
    __syncthreads();

    int buf = 0;
    for (int kt = 0; kt < NKT; ++kt) {
        if (kt + 1 < NKT) {
            a4 = *(const float4*)(Ag + (size_t)(kt + 1) * 8);
            b4 = *(const float4*)(Bg + (size_t)(kt + 1) * 8 * G3);
        }

        #pragma unroll
        for (int k = 0; k < 8; ++k) {
            const float* ap = &As2[buf][k][ty * 16];
            const float* bp = &Bs [buf][k][tx * 8];
            ulonglong2 a01 = *(const ulonglong2*)(ap);
            ulonglong2 a23 = *(const ulonglong2*)(ap + 4);
            ulonglong2 a45 = *(const ulonglong2*)(ap + 8);
            ulonglong2 a67 = *(const ulonglong2*)(ap + 12);
            ulonglong2 b03 = *(const ulonglong2*)(bp);
            ulonglong2 b47 = *(const ulonglong2*)(bp + 4);
            ull av0 = a01.x, av1 = a01.y, av2 = a23.x, av3 = a23.y;
            ull av4 = a45.x, av5 = a45.y, av6 = a67.x, av7 = a67.y;
            ull bv0 = b03.x, bv1 = b03.y, bv2 = b47.x, bv3 = b47.y;
            FMA_F32X2(acc[0][0], av0, bv0); FMA_F32X2(acc[0][1], av0, bv1);
            FMA_F32X2(acc[0][2], av0, bv2); FMA_F32X2(acc[0][3], av0, bv3);
            FMA_F32X2(acc[1][0], av1, bv0); FMA_F32X2(acc[1][1], av1, bv1);
            FMA_F32X2(acc[1][2], av1, bv2); FMA_F32X2(acc[1][3], av1, bv3);
            FMA_F32X2(acc[2][0], av2, bv0); FMA_F32X2(acc[2][1], av2, bv1);
            FMA_F32X2(acc[2][2], av2, bv2); FMA_F32X2(acc[2][3], av2, bv3);
            FMA_F32X2(acc[3][0], av3, bv0); FMA_F32X2(acc[3][1], av3, bv1);
            FMA_F32X2(acc[3][2], av3, bv2); FMA_F32X2(acc[3][3], av3, bv3);
            FMA_F32X2(acc[4][0], av4, bv0); FMA_F32X2(acc[4][1], av4, bv1);
            FMA_F32X2(acc[4][2], av4, bv2); FMA_F32X2(acc[4][3], av4, bv3);
            FMA_F32X2(acc[5][0], av5, bv0); FMA_F32X2(acc[5][1], av5, bv1);
            FMA_F32X2(acc[5][2], av5, bv2); FMA_F32X2(acc[5][3], av5, bv3);
            FMA_F32X2(acc[6][0], av6, bv0); FMA_F32X2(acc[6][1], av6, bv1);
            FMA_F32X2(acc[6][2], av6, bv2); FMA_F32X2(acc[6][3], av6, bv3);
            FMA_F32X2(acc[7][0], av7, bv0); FMA_F32X2(acc[7][1], av7, bv1);
            FMA_F32X2(acc[7][2], av7, bv2); FMA_F32X2(acc[7][3], av7, bv3);
        }

        if (kt + 1 < NKT) {
            int nb = buf ^ 1;
            *(float2*)&As2[nb][ak+0][2*arow] = make_float2(a4.x, a4.x);
            *(float2*)&As2[nb][ak+1][2*arow] = make_float2(a4.y, a4.y);
            *(float2*)&As2[nb][ak+2][2*arow] = make_float2(a4.z, a4.z);
            *(float2*)&As2[nb][ak+3][2*arow] = make_float2(a4.w, a4.w);
            *(float4*)&Bs[nb][bk][bc] = b4;
        }
        __syncthreads();
        buf ^= 1;
    }

    // epilogue: unpack, add bias, write gi in [t][b][3H] layout
    const int col0 = bx * 128 + tx * 8;
    float bv[8];
    #pragma unroll
    for (int j = 0; j < 8; ++j) bv[j] = bi[col0 + j];
    #pragma unroll
    for (int i = 0; i < 8; ++i) {
        int row = by * 128 + ty * 8 + i;       // = b*T + t
        int b = row >> 8, t = row & 255;
        float c[8];
        #pragma unroll
        for (int j = 0; j < 4; ++j) {
            c[2*j]   = __uint_as_float((unsigned)(acc[i][j] & 0xffffffffULL)) + bv[2*j];
            c[2*j+1] = __uint_as_float((unsigned)(acc[i][j] >> 32)) + bv[2*j+1];
        }
        float* dst = g_gi + ((size_t)t * B + b) * G3 + col0;
        *(float4*)(dst)     = make_float4(c[0], c[1], c[2], c[3]);
        *(float4*)(dst + 4) = make_float4(c[4], c[5], c[6], c[7]);
    }
}

// ---------------- persistent scan ----------------
#define SCAN_BLOCKS 128
#define US_STRIDE 2052                 // dup'd U row stride (floats)
#define SCAN_SMEM (24 * US_STRIDE * 4) // 196,992 B

__device__ __forceinline__ void grid_barrier() {
    __syncthreads();
    if (threadIdx.x == 0) {
        volatile unsigned* vg = &g_barg;
        unsigned my = *vg;
        __threadfence();
        if (atomicAdd(&g_barc, 1u) == SCAN_BLOCKS - 1u) {
            atomicExch(&g_barc, 0u);
            __threadfence();
            *vg = my + 1u;
        } else {
            while (*vg == my) {}
            __threadfence();
        }
    }
    __syncthreads();
}

__global__ void __launch_bounds__(256, 1)
scan_kernel(const float* __restrict__ bh) {
    extern __shared__ __align__(16) float Us[];   // [24][US_STRIDE] dup'd
    const int tid  = threadIdx.x;
    const int oloc = tid & 7;
    const int bg   = tid >> 3;          // 0..31  (b-pair index)
    const int o    = blockIdx.x * 8 + oloc;
    const int b0   = bg * 2;

    // stage this block's 24 U rows (3 gates x 8 o's), duplicated for f32x2
    const int blk_o0 = blockIdx.x * 8;
    for (int idx = tid; idx < 24 * 1024; idx += 256) {
        int r = idx >> 10;              // 0..23  (g*8 + ol)
        int k = idx & 1023;
        int g = r >> 3, ol = r & 7;
        float v = g_UT[(size_t)(g * H + blk_o0 + ol) * H + k];
        Us[r * US_STRIDE + 2*k]     = v;
        Us[r * US_STRIDE + 2*k + 1] = v;
    }
    __syncthreads();

    const float bh0 = bh[o];
    const float bh1 = bh[H + o];
    const float bh2 = bh[2*H + o];

    const float* ur0 = &Us[(0*8 + oloc) * US_STRIDE];
    const float* ur1 = &Us[(1*8 + oloc) * US_STRIDE];
    const float* ur2 = &Us[(2*8 + oloc) * US_STRIDE];

    for (int t = 0; t < T; ++t) {
        const float* hc = g_h2[t & 1] + (size_t)bg * (2*H);   // [k][2]
        float*       hn = g_h2[(t & 1) ^ 1];

        // input-gate values for this step (layout [t][b][3H])
        const float* gib = g_gi + (size_t)t * B * G3;
        float gi0a = gib[(size_t)(b0    ) * G3 +          o];
        float gi1a = gib[(size_t)(b0    ) * G3 + H      + o];
        float gi2a = gib[(size_t)(b0    ) * G3 + 2*H    + o];
        float gi0b = gib[(size_t)(b0 + 1) * G3 +          o];
        float gi1b = gib[(size_t)(b0 + 1) * G3 + H      + o];
        float gi2b = gib[(size_t)(b0 + 1) * G3 + 2*H    + o];

        ull acc0 = 0ULL, acc1 = 0ULL, acc2 = 0ULL;

        #pragma unroll 4
        for (int k = 0; k < H; k += 4) {
            ulonglong2 h01 = *(const ulonglong2*)(hc + 2*k);      // (k,k+1) pairs
            ulonglong2 h23 = *(const ulonglong2*)(hc + 2*k + 4);  // (k+2,k+3)
            ulonglong2 w0a = *(const ulonglong2*)(ur0 + 2*k);
            ulonglong2 w0b = *(const ulonglong2*)(ur0 + 2*k + 4);
            ulonglong2 w1a = *(const ulonglong2*)(ur1 + 2*k);
            ulonglong2 w1b = *(const ulonglong2*)(ur1 + 2*k + 4);
            ulonglong2 w2a = *(const ulonglong2*)(ur2 + 2*k);
            ulonglong2 w2b = *(const ulonglong2*)(ur2 + 2*k + 4);
            FMA_F32X2(acc0, h01.x, w0a.x); FMA_F32X2(acc1, h01.x, w1a.x); FMA_F32X2(acc2, h01.x, w2a.x);
            FMA_F32X2(acc0, h01.y, w0a.y); FMA_F32X2(acc1, h01.y, w1a.y); FMA_F32X2(acc2, h01.y, w2a.y);
            FMA_F32X2(acc0, h23.x, w0b.x); FMA_F32X2(acc1, h23.x, w1b.x); FMA_F32X2(acc2, h23.x, w2b.x);
            FMA_F32X2(acc0, h23.y, w0b.y); FMA_F32X2(acc1, h23.y, w1b.y); FMA_F32X2(acc2, h23.y, w2b.y);
        }

        float a00 = __uint_as_float((unsigned)(acc0 & 0xffffffffULL));
        float a10 = __uint_as_float((unsigned)(acc0 >> 32));
        float a01 = __uint_as_float((unsigned)(acc1 & 0xffffffffULL));
        float a11 = __uint_as_float((unsigned)(acc1 >> 32));
        float a02 = __uint_as_float((unsigned)(acc2 & 0xffffffffULL));
        float a12 = __uint_as_float((unsigned)(acc2 >> 32));

        float hoa = hc[2*o];      // h[o][b0]
        float hob = hc[2*o + 1];  // h[o][b0+1]

        float r_a = 1.f / (1.f + expf(-(gi0a + a00 + bh0)));
        float z_a = 1.f / (1.f + expf(-(gi1a + a01 + bh1)));
        float n_a = tanhf(gi2a + r_a * (a02 + bh2));
        float hna = (1.f - z_a) * n_a + z_a * hoa;

        float r_b = 1.f / (1.f + expf(-(gi0b + a10 + bh0)));
        float z_b = 1.f / (1.f + expf(-(gi1b + a11 + bh1)));
        float n_b = tanhf(gi2b + r_b * (a12 + bh2));
        float hnb = (1.f - z_b) * n_b + z_b * hob;

        *(float2*)&hn[(size_t)bg * (2*H) + 2*o] = make_float2(hna, hnb);

        grid_barrier();
    }
}

// ---------------- final FC + ReLU ----------------
__global__ void fc_kernel(const float* __restrict__ Wfc,
                          const float* __restrict__ bfc,
                          float* __restrict__ out) {
    int idx = blockIdx.x * blockDim.x + threadIdx.x;
    if (idx >= B * NC) return;
    int b = idx / NC, c = idx - b * NC;
    const float* h = g_h2[0] + (size_t)(b >> 1) * (2*H) + (b & 1);
    float s0 = bfc[c], s1 = 0.f;
    #pragma unroll 4
    for (int k = 0; k < H; k += 2) {
        s0 += h[2*k]     * Wfc[(size_t)(k    ) * NC + c];
        s1 += h[2*k + 2] * Wfc[(size_t)(k + 1) * NC + c];
    }
    out[idx] = fmaxf(s0 + s1, 0.f);
}

// ---------------- launcher ----------------
extern "C" void kernel_launch(void* const* d_in, const int* in_sizes, int n_in,
                              void* d_out, int out_size) {
    (void)in_sizes; (void)n_in; (void)out_size;
    const float* x    = (const float*)d_in[0];
    const float* c0   = (const float*)d_in[1];
    const float* c1   = (const float*)d_in[2];
    const float* c2   = (const float*)d_in[3];
    const float* c3   = (const float*)d_in[4];
    const float* bi   = (const float*)d_in[5];
    const float* U    = (const float*)d_in[6];
    const float* bh   = (const float*)d_in[7];
    const float* Wfc  = (const float*)d_in[8];
    const float* bfc  = (const float*)d_in[9];

    cudaFuncSetAttribute(scan_kernel, cudaFuncAttributeMaxDynamicSharedMemorySize, SCAN_SMEM);

    init_h_kernel<<<64, 256>>>();
    build_M_kernel<<<1, 256>>>(c0, c1, c2, c3);
    build_W_kernel<<<256, 256>>>();
    build_UT_kernel<<<dim3(96, 32), dim3(32, 8)>>>(U);
    gemm_gi_kernel<<<dim3(24, 128), 256>>>(x, bi);
    scan_kernel<<<SCAN_BLOCKS, 256, SCAN_SMEM>>>(bh);
    fc_kernel<<<(B * NC + 255) / 256, 256>>>(Wfc, bfc, (float*)d_out);
}

// round 4
// speedup vs baseline: 4.9226x; 1.8728x over previous
#include <cuda_runtime.h>
#include <math.h>
#include <stdint.h>

typedef unsigned long long ull;

// ---------------- problem constants ----------------
#define B   64
#define T   256
#define D   2048
#define H   1024
#define G3  3072
#define NC  1000
#define BT  (B*T)

#define FMA_F32X2(acc, a, b) \
    asm("fma.rn.f32x2 %0, %1, %2, %0;" : "+l"(acc) : "l"(a), "l"(b))

__device__ __forceinline__ float f2lo(ull v) { return __uint_as_float((unsigned)(v & 0xffffffffULL)); }
__device__ __forceinline__ float f2hi(ull v) { return __uint_as_float((unsigned)(v >> 32)); }

// ---------------- device scratch ----------------
__device__ __align__(16) float g_M2 [3*2048];            // [g][i1i2(32)][o1o2r2(64)]
__device__ __align__(16) float g_M34[3*16384];           // [g][r2][i3i4][o3o4] == [g][k(256)][64]
__device__ __align__(16) float g_UT [(size_t)G3*H];      // U^T: [j][k]
__device__ __align__(16) float g_P  [(size_t)BT*12288];  // [bt][g][o1o2][r2*64+i3i4]
__device__ __align__(16) float g_gi [(size_t)BT*G3];     // [t][b][3H]
__device__ __align__(16) float g_h  [2][B*H];            // ping-pong hidden [b][k]
__device__ unsigned g_barc;
__device__ unsigned g_barg;

// ---------------- init ----------------
__global__ void init_kernel() {
    int idx = blockIdx.x * blockDim.x + threadIdx.x;
    for (int i = idx; i < B*H; i += gridDim.x * blockDim.x) g_h[0][i] = 0.f;
    if (idx == 0) { g_barc = 0u; g_barg = 0u; }
}

// ---------------- build M2, M34 from TT cores ----------------
__global__ void build_M_kernel(const float* __restrict__ c0,
                               const float* __restrict__ c1,
                               const float* __restrict__ c2,
                               const float* __restrict__ c3) {
    for (int idx = threadIdx.x; idx < 3*2048; idx += blockDim.x) {
        int r2 = idx & 3, o2 = (idx>>2)&3, o1 = (idx>>4)&3;
        int i2 = (idx>>6)&7, i1 = (idx>>9)&3, g = idx>>11;
        float s = 0.f;
        #pragma unroll
        for (int r1 = 0; r1 < 4; ++r1)
            s += c0[g*64 + i1*16 + o1*4 + r1] *
                 c1[g*512 + r1*128 + i2*16 + o2*4 + r2];
        g_M2[idx] = s;
    }
    for (int idx = threadIdx.x; idx < 3*16384; idx += blockDim.x) {
        int o4 = idx & 7, o3 = (idx>>3)&7, i4 = (idx>>6)&7;
        int i3 = (idx>>9)&7, r2 = (idx>>12)&3, g = idx>>14;
        float s = 0.f;
        #pragma unroll
        for (int r3 = 0; r3 < 4; ++r3)
            s += c2[g*1024 + r2*256 + i3*32 + o3*4 + r3] *
                 c3[g*256  + r3*64  + i4*8  + o4];
        g_M34[idx] = s;
    }
}

// ---------------- transpose U [H,G3] -> UT [G3,H] ----------------
__global__ void build_UT_kernel(const float* __restrict__ U) {
    __shared__ float s[32][33];
    int j0 = blockIdx.x * 32;
    int k0 = blockIdx.y * 32;
    int tx = threadIdx.x, ty = threadIdx.y;
    #pragma unroll
    for (int r = ty; r < 32; r += 8)
        s[r][tx] = U[(size_t)(k0 + r) * G3 + j0 + tx];
    __syncthreads();
    #pragma unroll
    for (int r = ty; r < 32; r += 8)
        g_UT[(size_t)(j0 + r) * H + k0 + tx] = s[tx][r];
}

// ---------------- TT stage A ----------------
// P[bt][(g,o1o2,r2)=r(192)][i3i4(64)] = sum_{i1i2} v[bt][i1i2][i3i4] * M2[g][i1i2][ocr]
// grid: 2048 blocks x 8 bt, 256 threads; warp w -> bt w, lane l -> i3i4 pair l.
#define TTA_SMEM (32*192*8 + 8*2048*4)   // sM dup 49152 + sV 65536 = 114688
__global__ void __launch_bounds__(256)
ttA_kernel(const float* __restrict__ X) {
    extern __shared__ __align__(16) float smA[];
    float2* sM = (float2*)smA;                 // [k(32)][r(192)] duplicated
    float*  sV = smA + 2*32*192;               // [bt(8)][2048]

    const int tid = threadIdx.x;
    const int bt0 = blockIdx.x * 8;

    for (int i = tid; i < 32*192; i += 256) {
        int k = i / 192, r = i - k*192;
        int g = r >> 6, ocr = r & 63;
        float v = g_M2[g*2048 + k*64 + ocr];
        sM[k*192 + r] = make_float2(v, v);
    }
    {
        const float4* Xb = (const float4*)(X + (size_t)bt0 * D);
        float4* sv4 = (float4*)sV;
        #pragma unroll
        for (int i = tid; i < 8*2048/4; i += 256) sv4[i] = Xb[i];
    }
    __syncthreads();

    const int bt = tid >> 5;        // warp-uniform
    const int l  = tid & 31;        // i3i4 pair
    const float* vbase = sV + bt * 2048;
    const size_t prow = (size_t)(bt0 + bt) * 12288;

    for (int rg = 0; rg < 24; ++rg) {
        const int r0 = rg * 8;
        ull acc[8] = {0,0,0,0,0,0,0,0};
        #pragma unroll 4
        for (int k = 0; k < 32; ++k) {
            ull vv = *(const ull*)(vbase + k*64 + 2*l);
            const float2* mrow = sM + k*192 + r0;
            #pragma unroll
            for (int j = 0; j < 8; ++j) {
                ull mm = *(const ull*)(mrow + j);
                FMA_F32X2(acc[j], vv, mm);
            }
        }
        #pragma unroll
        for (int j = 0; j < 8; ++j) {
            int r = r0 + j;
            int g = r >> 6, o = (r >> 2) & 15, r2 = r & 3;
            float* dst = g_P + prow + ((size_t)g*16 + o)*256 + r2*64 + 2*l;
            *(float2*)dst = make_float2(f2lo(acc[j]), f2hi(acc[j]));
        }
    }
}

// ---------------- TT stage B ----------------
// per gate g: C[M=BT*16, 64] = P_g[M,256] @ M34g[256,64], + bias, scatter to gi[t][b][3H]
// block tile 128x64, K=256, 256 threads, microtile 8Mx4N (2 f32x2), A dup'd in smem.
__global__ void __launch_bounds__(256)
ttB_kernel(const float* __restrict__ bi) {
    __shared__ __align__(16) float2 Asd[2][16][128];   // dup A: [k][row]  32KB
    __shared__ __align__(16) float  Bs [2][16][64];    //                   8KB

    const int tid = threadIdx.x;
    const int g   = blockIdx.y;
    const int m0  = blockIdx.x * 128;
    const int tx  = tid & 15;      // N: cols tx*4..+3
    const int ty  = tid >> 4;      // M: rows ty*8..+7

    // staging assignment
    const int row0 = tid >> 2;             // 0..63
    const int kq   = (tid & 3) * 4;        // 0,4,8,12
    const int row1 = row0 + 64;
    const int bkr  = tid >> 4;             // B k-row 0..15
    const int bcc  = (tid & 15) * 4;       // B col

    const int mA0 = m0 + row0, mA1 = m0 + row1;
    const size_t offA0 = ((size_t)(mA0 >> 4) * 48 + g*16 + (mA0 & 15)) * 256;
    const size_t offA1 = ((size_t)(mA1 >> 4) * 48 + g*16 + (mA1 & 15)) * 256;
    const float* Mg = g_M34 + (size_t)g * 16384;

    ull acc[8][2];
    #pragma unroll
    for (int i = 0; i < 8; ++i) { acc[i][0] = 0ULL; acc[i][1] = 0ULL; }

    float4 a0 = *(const float4*)(g_P + offA0 + kq);
    float4 a1 = *(const float4*)(g_P + offA1 + kq);
    float4 b4 = *(const float4*)(Mg + (size_t)bkr * 64 + bcc);

    // stage tile 0
    Asd[0][kq+0][row0] = make_float2(a0.x, a0.x);
    Asd[0][kq+1][row0] = make_float2(a0.y, a0.y);
    Asd[0][kq+2][row0] = make_float2(a0.z, a0.z);
    Asd[0][kq+3][row0] = make_float2(a0.w, a0.w);
    Asd[0][kq+0][row1] = make_float2(a1.x, a1.x);
    Asd[0][kq+1][row1] = make_float2(a1.y, a1.y);
    Asd[0][kq+2][row1] = make_float2(a1.z, a1.z);
    Asd[0][kq+3][row1] = make_float2(a1.w, a1.w);
    *(float4*)&Bs[0][bkr][bcc] = b4;
    __syncthreads();

    int buf = 0;
    for (int kt = 0; kt < 16; ++kt) {
        if (kt < 15) {
            int k0 = (kt + 1) * 16;
            a0 = *(const float4*)(g_P + offA0 + k0 + kq);
            a1 = *(const float4*)(g_P + offA1 + k0 + kq);
            b4 = *(const float4*)(Mg + (size_t)(k0 + bkr) * 64 + bcc);
        }
        #pragma unroll
        for (int k = 0; k < 16; ++k) {
            const float2* ap = &Asd[buf][k][ty*8];
            ulonglong2 A01 = *(const ulonglong2*)(ap);
            ulonglong2 A23 = *(const ulonglong2*)(ap + 2);
            ulonglong2 A45 = *(const ulonglong2*)(ap + 4);
            ulonglong2 A67 = *(const ulonglong2*)(ap + 6);
            ulonglong2 Bv  = *(const ulonglong2*)&Bs[buf][k][tx*4];
            FMA_F32X2(acc[0][0], A01.x, Bv.x); FMA_F32X2(acc[0][1], A01.x, Bv.y);
            FMA_F32X2(acc[1][0], A01.y, Bv.x); FMA_F32X2(acc[1][1], A01.y, Bv.y);
            FMA_F32X2(acc[2][0], A23.x, Bv.x); FMA_F32X2(acc[2][1], A23.x, Bv.y);
            FMA_F32X2(acc[3][0], A23.y, Bv.x); FMA_F32X2(acc[3][1], A23.y, Bv.y);
            FMA_F32X2(acc[4][0], A45.x, Bv.x); FMA_F32X2(acc[4][1], A45.x, Bv.y);
            FMA_F32X2(acc[5][0], A45.y, Bv.x); FMA_F32X2(acc[5][1], A45.y, Bv.y);
            FMA_F32X2(acc[6][0], A67.x, Bv.x); FMA_F32X2(acc[6][1], A67.x, Bv.y);
            FMA_F32X2(acc[7][0], A67.y, Bv.x); FMA_F32X2(acc[7][1], A67.y, Bv.y);
        }
        if (kt < 15) {
            int nb = buf ^ 1;
            Asd[nb][kq+0][row0] = make_float2(a0.x, a0.x);
            Asd[nb][kq+1][row0] = make_float2(a0.y, a0.y);
            Asd[nb][kq+2][row0] = make_float2(a0.z, a0.z);
            Asd[nb][kq+3][row0] = make_float2(a0.w, a0.w);
            Asd[nb][kq+0][row1] = make_float2(a1.x, a1.x);
            Asd[nb][kq+1][row1] = make_float2(a1.y, a1.y);
            Asd[nb][kq+2][row1] = make_float2(a1.z, a1.z);
            Asd[nb][kq+3][row1] = make_float2(a1.w, a1.w);
            *(float4*)&Bs[nb][bkr][bcc] = b4;
        }
        __syncthreads();
        buf ^= 1;
    }

    // epilogue: bias + scatter to gi[t][b][3H]
    #pragma unroll
    for (int i = 0; i < 8; ++i) {
        int m  = m0 + ty*8 + i;
        int bt = m >> 4, oo = m & 15;
        int bb = bt >> 8, tt = bt & 255;
        const float* bp = bi + g*1024 + oo*64 + tx*4;
        float4 out;
        out.x = f2lo(acc[i][0]) + bp[0];
        out.y = f2hi(acc[i][0]) + bp[1];
        out.z = f2lo(acc[i][1]) + bp[2];
        out.w = f2hi(acc[i][1]) + bp[3];
        float* dst = g_gi + ((size_t)tt * B + bb) * G3 + g*1024 + oo*64 + tx*4;
        *(float4*)dst = out;
    }
}

// ---------------- persistent scan ----------------
#define SCAN_BLOCKS 128
#define US_STRIDE 1036                     // U row stride (floats), conflict-free
#define KC 512
#define SH_STRIDE 516                      // h row stride (floats)
#define SCAN_SMEM (24*US_STRIDE*4 + 64*SH_STRIDE*4)   // 99456 + 132096 = 231552

__global__ void __launch_bounds__(256, 1)
scan_kernel(const float* __restrict__ bh) {
    extern __shared__ __align__(16) float smem[];
    float* Us = smem;                      // [24][US_STRIDE]
    float* sH = smem + 24*US_STRIDE;       // [64][SH_STRIDE]

    const int tid    = threadIdx.x;
    const int oloc   = tid & 7;
    const int bslot  = tid >> 3;           // 0..31
    const int blk_o0 = blockIdx.x * 8;
    const int o      = blk_o0 + oloc;
    const int b0     = bslot, b1 = bslot + 32;

    // stage U rows (natural, non-duplicated)
    for (int i = tid; i < 24*1024; i += 256) {
        int r = i >> 10, k = i & 1023;
        int g = r >> 3, ol = r & 7;
        Us[r*US_STRIDE + k] = g_UT[(size_t)(g*H + blk_o0 + ol)*H + k];
    }
    __syncthreads();

    const float bh0 = bh[o], bh1 = bh[H+o], bh2 = bh[2*H+o];
    const float* ur0 = Us + (0*8 + oloc)*US_STRIDE;
    const float* ur1 = Us + (1*8 + oloc)*US_STRIDE;
    const float* ur2 = Us + (2*8 + oloc)*US_STRIDE;

    unsigned* barc = &g_barc;
    unsigned* barg = &g_barg;

    for (int t = 0; t < T; ++t) {
        const float* hc = g_h[t & 1];
        float*       hn = g_h[(t & 1) ^ 1];

        const float* gib = g_gi + (size_t)t * B * G3;
        float gi0a = __ldcg(gib + (size_t)b0*G3 +          o);
        float gi1a = __ldcg(gib + (size_t)b0*G3 + H      + o);
        float gi2a = __ldcg(gib + (size_t)b0*G3 + 2*H    + o);
        float gi0b = __ldcg(gib + (size_t)b1*G3 +          o);
        float gi1b = __ldcg(gib + (size_t)b1*G3 + H      + o);
        float gi2b = __ldcg(gib + (size_t)b1*G3 + 2*H    + o);
        float hoa  = __ldcg(hc + b0*H + o);
        float hob  = __ldcg(hc + b1*H + o);

        ull a0a=0ULL, a1a=0ULL, a2a=0ULL, a0b=0ULL, a1b=0ULL, a2b=0ULL;

        #pragma unroll
        for (int c = 0; c < 2; ++c) {
            const int k0 = c * KC;
            __syncthreads();
            // stage h chunk [64][KC] via L2 (.cg: no stale-L1 hazard)
            for (int i = tid; i < 64*(KC/4); i += 256) {
                int b = i >> 7;               // KC/4 = 128
                int q = i & 127;
                float4 v = __ldcg(((const float4*)(hc + (size_t)b*H + k0)) + q);
                *(float4*)(sH + b*SH_STRIDE + q*4) = v;
            }
            __syncthreads();

            const float* ha = sH + b0*SH_STRIDE;
            const float* hb = sH + b1*SH_STRIDE;
            const float* w0 = ur0 + k0;
            const float* w1 = ur1 + k0;
            const float* w2 = ur2 + k0;

            #pragma unroll 2
            for (int k = 0; k < KC; k += 8) {
                ulonglong2 hA0 = *(const ulonglong2*)(ha + k);
                ulonglong2 hB0 = *(const ulonglong2*)(hb + k);
                ulonglong2 W0a = *(const ulonglong2*)(w0 + k);
                ulonglong2 W1a = *(const ulonglong2*)(w1 + k);
                ulonglong2 W2a = *(const ulonglong2*)(w2 + k);
                FMA_F32X2(a0a, hA0.x, W0a.x); FMA_F32X2(a1a, hA0.x, W1a.x); FMA_F32X2(a2a, hA0.x, W2a.x);
                FMA_F32X2(a0b, hB0.x, W0a.x); FMA_F32X2(a1b, hB0.x, W1a.x); FMA_F32X2(a2b, hB0.x, W2a.x);
                FMA_F32X2(a0a, hA0.y, W0a.y); FMA_F32X2(a1a, hA0.y, W1a.y); FMA_F32X2(a2a, hA0.y, W2a.y);
                FMA_F32X2(a0b, hB0.y, W0a.y); FMA_F32X2(a1b, hB0.y, W1a.y); FMA_F32X2(a2b, hB0.y, W2a.y);
                ulonglong2 hA1 = *(const ulonglong2*)(ha + k + 4);
                ulonglong2 hB1 = *(const ulonglong2*)(hb + k + 4);
                ulonglong2 W0b = *(const ulonglong2*)(w0 + k + 4);
                ulonglong2 W1b = *(const ulonglong2*)(w1 + k + 4);
                ulonglong2 W2b = *(const ulonglong2*)(w2 + k + 4);
                FMA_F32X2(a0a, hA1.x, W0b.x); FMA_F32X2(a1a, hA1.x, W1b.x); FMA_F32X2(a2a, hA1.x, W2b.x);
                FMA_F32X2(a0b, hB1.x, W0b.x); FMA_F32X2(a1b, hB1.x, W1b.x); FMA_F32X2(a2b, hB1.x, W2b.x);
                FMA_F32X2(a0a, hA1.y, W0b.y); FMA_F32X2(a1a, hA1.y, W1b.y); FMA_F32X2(a2a, hA1.y, W2b.y);
                FMA_F32X2(a0b, hB1.y, W0b.y); FMA_F32X2(a1b, hB1.y, W1b.y); FMA_F32X2(a2b, hB1.y, W2b.y);
            }
        }

        // reduce k-pairs, GRU pointwise update
        float A00 = f2lo(a0a) + f2hi(a0a);
        float A01 = f2lo(a1a) + f2hi(a1a);
        float A02 = f2lo(a2a) + f2hi(a2a);
        float A10 = f2lo(a0b) + f2hi(a0b);
        float A11 = f2lo(a1b) + f2hi(a1b);
        float A12 = f2lo(a2b) + f2hi(a2b);

        float r_a = 1.f / (1.f + expf(-(gi0a + A00 + bh0)));
        float z_a = 1.f / (1.f + expf(-(gi1a + A01 + bh1)));
        float n_a = tanhf(gi2a + r_a * (A02 + bh2));
        hn[b0*H + o] = (1.f - z_a) * n_a + z_a * hoa;

        float r_b = 1.f / (1.f + expf(-(gi0b + A10 + bh0)));
        float z_b = 1.f / (1.f + expf(-(gi1b + A11 + bh1)));
        float n_b = tanhf(gi2b + r_b * (A12 + bh2));
        hn[b1*H + o] = (1.f - z_b) * n_b + z_b * hob;

        // grid barrier: release/acquire at L2, no L1 flush, monotone counters
        __syncthreads();
        if (tid == 0) {
            unsigned old;
            asm volatile("atom.add.release.gpu.u32 %0, [%1], 1;"
                         : "=r"(old) : "l"(barc) : "memory");
            unsigned tgt = (unsigned)(t + 1);
            if (old == tgt * SCAN_BLOCKS - 1u) {
                asm volatile("st.release.gpu.u32 [%0], %1;" :: "l"(barg), "r"(tgt) : "memory");
            } else {
                unsigned cur;
                do {
                    asm volatile("ld.acquire.gpu.u32 %0, [%1];" : "=r"(cur) : "l"(barg) : "memory");
                } while (cur < tgt);
            }
        }
        __syncthreads();
    }
}

// ---------------- final FC + ReLU ----------------
__global__ void fc_kernel(const float* __restrict__ Wfc,
                          const float* __restrict__ bfc,
                          float* __restrict__ out) {
    int idx = blockIdx.x * blockDim.x + threadIdx.x;
    if (idx >= B * NC) return;
    int b = idx / NC, c = idx - b * NC;
    const float* h = g_h[0] + (size_t)b * H;   // T even -> final state in buffer 0
    float s0 = bfc[c], s1 = 0.f, s2 = 0.f, s3 = 0.f;
    #pragma unroll 4
    for (int k = 0; k < H; k += 4) {
        float4 hv = *(const float4*)(h + k);
        s0 += hv.x * Wfc[(size_t)(k    ) * NC + c];
        s1 += hv.y * Wfc[(size_t)(k + 1) * NC + c];
        s2 += hv.z * Wfc[(size_t)(k + 2) * NC + c];
        s3 += hv.w * Wfc[(size_t)(k + 3) * NC + c];
    }
    out[idx] = fmaxf((s0 + s1) + (s2 + s3), 0.f);
}

// ---------------- launcher ----------------
extern "C" void kernel_launch(void* const* d_in, const int* in_sizes, int n_in,
                              void* d_out, int out_size) {
    (void)in_sizes; (void)n_in; (void)out_size;
    const float* x    = (const float*)d_in[0];
    const float* c0   = (const float*)d_in[1];
    const float* c1   = (const float*)d_in[2];
    const float* c2   = (const float*)d_in[3];
    const float* c3   = (const float*)d_in[4];
    const float* bi   = (const float*)d_in[5];
    const float* U    = (const float*)d_in[6];
    const float* bh   = (const float*)d_in[7];
    const float* Wfc  = (const float*)d_in[8];
    const float* bfc  = (const float*)d_in[9];

    cudaFuncSetAttribute(ttA_kernel,  cudaFuncAttributeMaxDynamicSharedMemorySize, TTA_SMEM);
    cudaFuncSetAttribute(scan_kernel, cudaFuncAttributeMaxDynamicSharedMemorySize, SCAN_SMEM);

    init_kernel<<<64, 256>>>();
    build_M_kernel<<<1, 256>>>(c0, c1, c2, c3);
    build_UT_kernel<<<dim3(96, 32), dim3(32, 8)>>>(U);
    ttA_kernel<<<2048, 256, TTA_SMEM>>>(x);
    ttB_kernel<<<dim3(2048, 3), 256>>>(bi);
    scan_kernel<<<SCAN_BLOCKS, 256, SCAN_SMEM>>>(bh);
    fc_kernel<<<(B * NC + 255) / 256, 256>>>(Wfc, bfc, (float*)d_out);
}